// round 7
// baseline (speedup 1.0000x reference)
#include <cuda_runtime.h>
#include <cuda_fp16.h>

typedef unsigned long long u64;

// ---------------- f32x2 helpers (sm_100+) ----------------
__device__ __forceinline__ u64 pack2(float x) {
    u64 r;
    asm("mov.b64 %0, {%1, %1};" : "=l"(r) : "f"(x));
    return r;
}
__device__ __forceinline__ u64 pack2f(float lo, float hi) {
    u64 r;
    asm("mov.b64 %0, {%1, %2};" : "=l"(r) : "f"(lo), "f"(hi));
    return r;
}
__device__ __forceinline__ void fma2(u64& d, u64 a, u64 b) {
    asm("fma.rn.f32x2 %0, %1, %2, %3;" : "=l"(d) : "l"(a), "l"(b), "l"(d));
}
__device__ __forceinline__ u64 fma2_3(u64 a, u64 b, u64 c) {
    u64 d;
    asm("fma.rn.f32x2 %0, %1, %2, %3;" : "=l"(d) : "l"(a), "l"(b), "l"(c));
    return d;
}
__device__ __forceinline__ u64 mul2_(u64 a, u64 b) {
    u64 d; asm("mul.rn.f32x2 %0, %1, %2;" : "=l"(d) : "l"(a), "l"(b)); return d;
}
__device__ __forceinline__ u64 add2_(u64 a, u64 b) {
    u64 d; asm("add.rn.f32x2 %0, %1, %2;" : "=l"(d) : "l"(a), "l"(b)); return d;
}
__device__ __forceinline__ u64 sub2_(u64 a, u64 b) {
    u64 d; asm("sub.rn.f32x2 %0, %1, %2;" : "=l"(d) : "l"(a), "l"(b)); return d;
}
__device__ __forceinline__ void unpack2(u64 v, float& lo, float& hi) {
    asm("mov.b64 {%0, %1}, %2;" : "=f"(lo), "=f"(hi) : "l"(v));
}

// packed exact elu on a unit pair
__device__ __forceinline__ u64 elu2(u64 v) {
    float lo, hi; unpack2(v, lo, hi);
    u64 m = pack2f(fminf(lo, 0.f), fminf(hi, 0.f));
    u64 s = mul2_(m, 0x3FB8AA3B3FB8AA3BULL);   // * log2(e)
    float sl, sh; unpack2(s, sl, sh);
    float el, eh;
    asm("ex2.approx.f32 %0, %1;" : "=f"(el) : "f"(sl));
    asm("ex2.approx.f32 %0, %1;" : "=f"(eh) : "f"(sh));
    u64 e = pack2f(el, eh);
    u64 p = sub2_(v, m);
    return add2_(add2_(e, p), 0xBF800000BF800000ULL);
}
__device__ __forceinline__ float elu_f(float x) {
    return fmaxf(x, 0.f) + __expf(fminf(x, 0.f)) - 1.f;
}

// ---------------- scratch ----------------
__device__ float g_buf0[524288];
__device__ float g_buf1[65536];
__device__ float g_buf2[8192];

// ======================= shared LSTM bodies =======================
// xsT: transposed x [8*CIN rows][COLSP], hsm2: [80 rows][COLSP] half2
template <int CIN, int COLSP, int NSEQ, int DIR>
__device__ __forceinline__ void lstm1_dir(
    const float* __restrict__ xsT, const float4* __restrict__ WU,
    const float4* __restrict__ Bv, __half2* __restrict__ hsm2, const int* col)
{
    u64 h[NSEQ][5], c[NSEQ][5];
#pragma unroll
    for (int q = 0; q < NSEQ; q++)
#pragma unroll
        for (int m = 0; m < 5; m++) { h[q][m] = 0ULL; c[q][m] = 0ULL; }

#pragma unroll 1
    for (int s = 0; s < 8; s++) {
        const int t = DIR ? (7 - s) : s;
        u64 acc[NSEQ][20];
#pragma unroll
        for (int j = 0; j < 10; j++) {
            ulonglong2 bq = *(const ulonglong2*)&Bv[j];
            int p = (j >> 1) * 4 + 2 * (j & 1);
#pragma unroll
            for (int q = 0; q < NSEQ; q++) { acc[q][p] = bq.x; acc[q][p + 1] = bq.y; }
        }
#pragma unroll
        for (int k = 0; k < CIN; k++) {
            u64 px[NSEQ];
#pragma unroll
            for (int q = 0; q < NSEQ; q++)
                px[q] = pack2(xsT[(t * CIN + k) * COLSP + col[q]]);
#pragma unroll
            for (int j = 0; j < 10; j++) {
                ulonglong2 wq = *(const ulonglong2*)&WU[k * 10 + j];
                int p = (j >> 1) * 4 + 2 * (j & 1);
#pragma unroll
                for (int q = 0; q < NSEQ; q++) {
                    fma2(acc[q][p], px[q], wq.x);
                    fma2(acc[q][p + 1], px[q], wq.y);
                }
            }
        }
#pragma unroll
        for (int kp = 0; kp < 5; kp++) {
            float hv[NSEQ][2];
#pragma unroll
            for (int q = 0; q < NSEQ; q++) unpack2(h[q][kp], hv[q][0], hv[q][1]);
#pragma unroll
            for (int sub = 0; sub < 2; sub++) {
                const int k = kp * 2 + sub;
                u64 ph[NSEQ];
#pragma unroll
                for (int q = 0; q < NSEQ; q++) ph[q] = pack2(hv[q][sub]);
#pragma unroll
                for (int j = 0; j < 10; j++) {
                    ulonglong2 wq = *(const ulonglong2*)&WU[(CIN + k) * 10 + j];
                    int p = (j >> 1) * 4 + 2 * (j & 1);
#pragma unroll
                    for (int q = 0; q < NSEQ; q++) {
                        fma2(acc[q][p], ph[q], wq.x);
                        fma2(acc[q][p + 1], ph[q], wq.y);
                    }
                }
            }
        }
        // gates i,f,g,o: c = elu2(f)*c + elu2(i)*elu2(g); h = elu2(o)*elu2(c)
#pragma unroll
        for (int mp = 0; mp < 5; mp++) {
#pragma unroll
            for (int q = 0; q < NSEQ; q++) {
                u64 ei = elu2(acc[q][mp * 4 + 0]);
                u64 ef = elu2(acc[q][mp * 4 + 1]);
                u64 eg = elu2(acc[q][mp * 4 + 2]);
                u64 eo = elu2(acc[q][mp * 4 + 3]);
                c[q][mp] = fma2_3(ef, c[q][mp], mul2_(ei, eg));
                h[q][mp] = mul2_(eo, elu2(c[q][mp]));
                float l, hh; unpack2(h[q][mp], l, hh);
                hsm2[(DIR * 40 + t * 5 + mp) * COLSP + col[q]] = __floats2half2_rn(l, hh);
            }
        }
    }
}

template <int COLSP, int NSEQ, int DIR>
__device__ __forceinline__ void lstm2_dir(
    const __half2* __restrict__ hsm2, const float4* __restrict__ sV,
    const float4* __restrict__ sR, const float4* __restrict__ sC,
    const int* col, float* h2out)
{
    const ulonglong2 rq = *(const ulonglong2*)&sR[DIR];
    const ulonglong2 cq = *(const ulonglong2*)&sC[DIR];

    u64 y0[NSEQ][8], y1[NSEQ][8];
#pragma unroll
    for (int q = 0; q < NSEQ; q++)
#pragma unroll
        for (int t = 0; t < 8; t++) { y0[q][t] = cq.x; y1[q][t] = cq.y; }

#pragma unroll
    for (int d2 = 0; d2 < 2; d2++) {
#pragma unroll
        for (int up = 0; up < 5; up++) {
            ulonglong2 v0 = *(const ulonglong2*)&sV[DIR * 20 + d2 * 10 + 2 * up];
            ulonglong2 v1 = *(const ulonglong2*)&sV[DIR * 20 + d2 * 10 + 2 * up + 1];
#pragma unroll
            for (int t = 0; t < 8; t++) {
                const int row = d2 * 40 + t * 5 + up;
#pragma unroll
                for (int q = 0; q < NSEQ; q++) {
                    float2 f2 = __half22float2(hsm2[row * COLSP + col[q]]);
                    u64 a0 = pack2(f2.x), a1 = pack2(f2.y);
                    fma2(y0[q][t], a0, v0.x); fma2(y1[q][t], a0, v0.y);
                    fma2(y0[q][t], a1, v1.x); fma2(y1[q][t], a1, v1.y);
                }
            }
        }
    }

#pragma unroll
    for (int q = 0; q < NSEQ; q++) {
        float hh = 0.f, cc = 0.f;
#define REC_STEP(T)                                                  \
        {                                                            \
            u64 z0 = y0[q][T], z1 = y1[q][T];                        \
            u64 pa = pack2(hh);                                      \
            fma2(z0, pa, rq.x); fma2(z1, pa, rq.y);                  \
            u64 e = elu2(z0);                                        \
            float ei, ef; unpack2(e, ei, ef);                        \
            float zg, zo; unpack2(z1, zg, zo);                       \
            cc = ef * cc + ei * zg;                                  \
            hh = elu_f(zo) * cc;                                     \
        }
        if (DIR == 0) {
            REC_STEP(0) REC_STEP(1) REC_STEP(2) REC_STEP(3)
            REC_STEP(4) REC_STEP(5) REC_STEP(6) REC_STEP(7)
        } else {
            REC_STEP(7) REC_STEP(6) REC_STEP(5) REC_STEP(4)
            REC_STEP(3) REC_STEP(2) REC_STEP(1) REC_STEP(0)
        }
#undef REC_STEP
        h2out[q] = hh;
    }
}

// ---------------- shared staging helpers ----------------
template <int CIN, int NT>
__device__ __forceinline__ void stage_weights(
    float4* sWU, float4* sBias, float4* sV, float4* sR, float4* sC,
    const float* wf, const float* uf, const float* bf,
    const float* wb, const float* ub, const float* bb,
    const float* v2f, const float* r2f, const float* c2f,
    const float* v2b, const float* r2b, const float* c2b, int tid)
{
    constexpr int KTOT = CIN + 10;
    for (int i = tid; i < 2 * KTOT * 10; i += NT) {
        int d = i / (KTOT * 10);
        int r = i - d * (KTOT * 10);
        int k = r / 10;
        int j = r - k * 10;
        const float* W = (k < CIN) ? ((d ? wb : wf) + k * 40)
                                   : ((d ? ub : uf) + (k - CIN) * 40);
        int mp = j >> 1, gp = j & 1;
        int c0 = (2 * gp) * 10 + 2 * mp;
        int c2 = (2 * gp + 1) * 10 + 2 * mp;
        sWU[i] = make_float4(W[c0], W[c0 + 1], W[c2], W[c2 + 1]);
    }
    for (int i = tid; i < 20; i += NT) {
        int d = i / 10, j = i % 10;
        const float* B = d ? bb : bf;
        int mp = j >> 1, gp = j & 1;
        int c0 = (2 * gp) * 10 + 2 * mp;
        int c2 = (2 * gp + 1) * 10 + 2 * mp;
        sBias[i] = make_float4(B[c0], B[c0 + 1], B[c2], B[c2 + 1]);
    }
    for (int i = tid; i < 40; i += NT) {
        int d = i / 20, k = i % 20;
        const float* V = d ? v2b : v2f;
        sV[i] = make_float4(V[k * 4 + 0], V[k * 4 + 1], V[k * 4 + 2], V[k * 4 + 3]);
    }
    if (tid < 2) {
        const float* R = tid ? r2b : r2f;
        const float* C = tid ? c2b : c2f;
        sR[tid] = make_float4(R[0], R[1], R[2], R[3]);
        sC[tid] = make_float4(C[0], C[1], C[2], C[3]);
    }
}

__host__ __device__ constexpr int smem_main_floats(int CIN, int S) {
    return 80 * (S + 1) + 8 * CIN * (S + 1) + (2 * (CIN + 10) * 10 + 64) * 4;
}
__host__ __device__ constexpr int smem_pair_floats(int CIN, int S) {
    return 80 * (S / 2 + 1) + 8 * CIN * (S / 2 + 1) + (2 * (CIN + 10) * 10 + 64) * 4;
}

// ============ main kernel: 2 seqs/thread, warp parity = direction ============
// S threads handle S sequences. Warp-pair wp covers seqs [wp*64, wp*64+64):
//   lane l of each warp in the pair -> seqA = wp*64+2l (col wp*64+l),
//                                      seqB = seqA+1   (col wp*64+32+l)
template <int CIN, int S, int MINB>
__global__ void __launch_bounds__(S, MINB)
agg_main(const float* __restrict__ in, float* __restrict__ out,
         const float* __restrict__ wf, const float* __restrict__ uf, const float* __restrict__ bf,
         const float* __restrict__ wb, const float* __restrict__ ub, const float* __restrict__ bb,
         const float* __restrict__ v2f, const float* __restrict__ r2f, const float* __restrict__ c2f,
         const float* __restrict__ v2b, const float* __restrict__ r2b, const float* __restrict__ c2b)
{
    extern __shared__ float smem[];
    constexpr int KTOT = CIN + 10;
    constexpr int COLSP = S + 1;

    __half2* hsm2  = (__half2*)smem;                       // [80][COLSP]
    float4*  sWU   = (float4*)(smem + 80 * COLSP);
    float4*  sBias = sWU + 2 * KTOT * 10;
    float4*  sV    = sBias + 20;
    float4*  sR    = sV + 40;
    float4*  sC    = sR + 2;
    float*   xsT   = (float*)(sC + 2);                     // [8*CIN][COLSP]

    const int tid = threadIdx.x;
    stage_weights<CIN, S>(sWU, sBias, sV, sR, sC,
                          wf, uf, bf, wb, ub, bb, v2f, r2f, c2f, v2b, r2b, c2b, tid);
    {
        long long base = (long long)blockIdx.x * S * (8 * CIN);
        const int total = S * 8 * CIN;
        for (int i = tid; i < total; i += S) {
            int seq = i / (8 * CIN);
            int row = i - seq * (8 * CIN);
            int w = seq >> 6, r = seq & 63;
            int colm = w * 64 + ((r & 1) << 5) + (r >> 1);
            xsT[row * COLSP + colm] = in[base + i];
        }
    }
    __syncthreads();

    const int wid = tid >> 5;
    const int lane = tid & 31;
    const int dir = wid & 1;
    const int wp = wid >> 1;
    int col[2] = { wp * 64 + lane, wp * 64 + 32 + lane };
    const int seqA = wp * 64 + 2 * lane;

    const float4* WU = sWU + dir * KTOT * 10;
    const float4* Bv = sBias + dir * 10;

    if (dir == 0) lstm1_dir<CIN, COLSP, 2, 0>(xsT, WU, Bv, hsm2, col);
    else          lstm1_dir<CIN, COLSP, 2, 1>(xsT, WU, Bv, hsm2, col);
    __syncthreads();

    float h2[2];
    if (dir == 0) lstm2_dir<COLSP, 2, 0>(hsm2, sV, sR, sC, col, h2);
    else          lstm2_dir<COLSP, 2, 1>(hsm2, sV, sR, sC, col, h2);

    if (dir == 1) { xsT[col[0]] = h2[0]; xsT[col[1]] = h2[1]; }
    __syncthreads();
    if (dir == 0) {
        float oA = xsT[col[0]], oB = xsT[col[1]];
        out[blockIdx.x * S + seqA]     = 1.f / (1.f + __expf(-0.5f * (h2[0] + oA)));
        out[blockIdx.x * S + seqA + 1] = 1.f / (1.f + __expf(-0.5f * (h2[1] + oB)));
    }
}

// ============ pair kernel: 1 seq/thread (tail levels) ============
// S threads handle S/2 sequences: warp parity = dir; lane l of warp-pair wp -> seq wp*32+l.
template <int CIN, int S, int MINB>
__global__ void __launch_bounds__(S, MINB)
agg_pair(const float* __restrict__ in, float* __restrict__ out,
         const float* __restrict__ wf, const float* __restrict__ uf, const float* __restrict__ bf,
         const float* __restrict__ wb, const float* __restrict__ ub, const float* __restrict__ bb,
         const float* __restrict__ v2f, const float* __restrict__ r2f, const float* __restrict__ c2f,
         const float* __restrict__ v2b, const float* __restrict__ r2b, const float* __restrict__ c2b)
{
    extern __shared__ float smem[];
    constexpr int KTOT = CIN + 10;
    constexpr int NS = S / 2;
    constexpr int COLSP = NS + 1;

    __half2* hsm2  = (__half2*)smem;
    float4*  sWU   = (float4*)(smem + 80 * COLSP);
    float4*  sBias = sWU + 2 * KTOT * 10;
    float4*  sV    = sBias + 20;
    float4*  sR    = sV + 40;
    float4*  sC    = sR + 2;
    float*   xsT   = (float*)(sC + 2);

    const int tid = threadIdx.x;
    stage_weights<CIN, S>(sWU, sBias, sV, sR, sC,
                          wf, uf, bf, wb, ub, bb, v2f, r2f, c2f, v2b, r2b, c2b, tid);
    {
        long long base = (long long)blockIdx.x * NS * (8 * CIN);
        const int total = NS * 8 * CIN;
        for (int i = tid; i < total; i += S) {
            int seq = i / (8 * CIN);
            int row = i - seq * (8 * CIN);
            xsT[row * COLSP + seq] = in[base + i];
        }
    }
    __syncthreads();

    const int wid = tid >> 5;
    const int lane = tid & 31;
    const int dir = wid & 1;
    const int wp = wid >> 1;
    int col[1] = { wp * 32 + lane };

    const float4* WU = sWU + dir * KTOT * 10;
    const float4* Bv = sBias + dir * 10;

    if (dir == 0) lstm1_dir<CIN, COLSP, 1, 0>(xsT, WU, Bv, hsm2, col);
    else          lstm1_dir<CIN, COLSP, 1, 1>(xsT, WU, Bv, hsm2, col);
    __syncthreads();

    float h2[1];
    if (dir == 0) lstm2_dir<COLSP, 1, 0>(hsm2, sV, sR, sC, col, h2);
    else          lstm2_dir<COLSP, 1, 1>(hsm2, sV, sR, sC, col, h2);

    if (dir == 1) xsT[col[0]] = h2[0];
    __syncthreads();
    if (dir == 0)
        out[blockIdx.x * NS + col[0]] = 1.f / (1.f + __expf(-0.5f * (h2[0] + xsT[col[0]])));
}

extern "C" void kernel_launch(void* const* d_in, const int* in_sizes, int n_in,
                              void* d_out, int out_size)
{
    const float* x   = (const float*)d_in[0];
    const float* w0f = (const float*)d_in[1];
    const float* u0f = (const float*)d_in[2];
    const float* b0f = (const float*)d_in[3];
    const float* w0b = (const float*)d_in[4];
    const float* u0b = (const float*)d_in[5];
    const float* b0b = (const float*)d_in[6];
    const float* w1f = (const float*)d_in[7];
    const float* u1f = (const float*)d_in[8];
    const float* b1f = (const float*)d_in[9];
    const float* w1b = (const float*)d_in[10];
    const float* u1b = (const float*)d_in[11];
    const float* b1b = (const float*)d_in[12];
    const float* vF  = (const float*)d_in[13];
    const float* rF  = (const float*)d_in[14];
    const float* cF  = (const float*)d_in[15];
    const float* vB  = (const float*)d_in[16];
    const float* rB  = (const float*)d_in[17];
    const float* cB  = (const float*)d_in[18];
    float* out = (float*)d_out;

    float *buf0, *buf1, *buf2;
    cudaGetSymbolAddress((void**)&buf0, g_buf0);
    cudaGetSymbolAddress((void**)&buf1, g_buf1);
    cudaGetSymbolAddress((void**)&buf2, g_buf2);

    typedef void (*KFn)(const float*, float*,
                        const float*, const float*, const float*,
                        const float*, const float*, const float*,
                        const float*, const float*, const float*,
                        const float*, const float*, const float*);
    KFn k0 = agg_main<5, 128, 2>;
    KFn k1 = agg_main<1, 128, 2>;
    KFn k2 = agg_pair<1, 128, 2>;
    KFn k3 = agg_pair<1, 64, 2>;

    const size_t sm0 = (size_t)smem_main_floats(5, 128) * sizeof(float);
    const size_t sm1 = (size_t)smem_main_floats(1, 128) * sizeof(float);
    const size_t sm2 = (size_t)smem_pair_floats(1, 128) * sizeof(float);
    const size_t sm3 = (size_t)smem_pair_floats(1, 64) * sizeof(float);
    cudaFuncSetAttribute(k0, cudaFuncAttributeMaxDynamicSharedMemorySize, (int)sm0);
    cudaFuncSetAttribute(k1, cudaFuncAttributeMaxDynamicSharedMemorySize, (int)sm1);
    cudaFuncSetAttribute(k2, cudaFuncAttributeMaxDynamicSharedMemorySize, (int)sm2);
    cudaFuncSetAttribute(k3, cudaFuncAttributeMaxDynamicSharedMemorySize, (int)sm3);

    // level 0: 524288 seqs
    k0<<<524288 / 128, 128, sm0>>>(x, buf0,
        w0f, u0f, b0f, w0b, u0b, b0b, vF, rF, cF, vB, rB, cB);

    // level 1: 65536 seqs
    k1<<<65536 / 128, 128, sm1>>>(buf0, buf1,
        w1f + 0 * 40, u1f + 0 * 400, b1f + 0 * 40,
        w1b + 0 * 40, u1b + 0 * 400, b1b + 0 * 40,
        vF + 1 * 80, rF + 1 * 4, cF + 1 * 4,
        vB + 1 * 80, rB + 1 * 4, cB + 1 * 4);

    // level 2: 8192 seqs, 64 seqs/block
    k2<<<8192 / 64, 128, sm2>>>(buf1, buf2,
        w1f + 1 * 40, u1f + 1 * 400, b1f + 1 * 40,
        w1b + 1 * 40, u1b + 1 * 400, b1b + 1 * 40,
        vF + 2 * 80, rF + 2 * 4, cF + 2 * 4,
        vB + 2 * 80, rB + 2 * 4, cB + 2 * 4);

    // level 3: 1024 seqs, 32 seqs/block
    k3<<<1024 / 32, 64, sm3>>>(buf2, out,
        w1f + 2 * 40, u1f + 2 * 400, b1f + 2 * 40,
        w1b + 2 * 40, u1b + 2 * 400, b1b + 2 * 40,
        vF + 3 * 80, rF + 3 * 4, cF + 3 * 4,
        vB + 3 * 80, rB + 3 * 4, cB + 3 * 4);
}